// round 1
// baseline (speedup 1.0000x reference)
#include <cuda_runtime.h>
#include <math.h>

#define THREADS      256
#define IMGS_PER_BLK 128
#define PX_STRIDE    129          // floats per k-row in transposed pixel buffer
#define PX_ROWS      56           // 2 image rows per patch-row tile
#define W_FLOATS     7840         // 10 x 784
#define PX_FLOATS    (PX_ROWS * PX_STRIDE)   // 7224
#define SMEM_FLOATS  (PX_FLOATS + W_FLOATS + 16)

__device__ __forceinline__ void fma2(unsigned long long &acc,
                                     unsigned long long a,
                                     unsigned long long b) {
    asm("fma.rn.f32x2 %0, %1, %2, %0;" : "+l"(acc) : "l"(a), "l"(b));
}
__device__ __forceinline__ unsigned long long pack2(float lo, float hi) {
    unsigned long long r;
    asm("mov.b64 %0, {%1, %2};" : "=l"(r) : "f"(lo), "f"(hi));
    return r;
}
__device__ __forceinline__ float2 unpack2(unsigned long long v) {
    float lo, hi;
    asm("mov.b64 {%0, %1}, %2;" : "=f"(lo), "=f"(hi) : "l"(v));
    return make_float2(lo, hi);
}

__global__ void __launch_bounds__(THREADS)
quanv_kernel(const float* __restrict__ x,
             const float* __restrict__ W,
             const float* __restrict__ b,
             float* __restrict__ out)
{
    extern __shared__ float smem[];
    float* s_px = smem;                 // [56][129] transposed pixel tile
    float* s_W  = smem + PX_FLOATS;     // 7840 floats, 16B aligned (7224*4 % 16 == 0)
    float* s_b  = s_W + W_FLOATS;       // 10 floats
    float* s_mg = smem;                 // merge buffer aliases pixel buffer at the end

    const int tid  = threadIdx.x;
    const int lane = tid & 31;
    const int warp = tid >> 5;
    const int imgcol = (warp & 3) * 32 + lane;  // 0..127 within block
    const int chalf  = warp >> 2;               // 0: patch cols 0..6, 1: cols 7..13
    const int cbase  = chalf * 7;

    const long imgBase = (long)blockIdx.x * IMGS_PER_BLK;
    const float* xg = x + imgBase * 784;

    // ---- cooperative load of W (and b) into shared ----
    {
        const float4* Wg = (const float4*)W;
        float4* Ws4 = (float4*)s_W;
        #pragma unroll
        for (int i = tid; i < W_FLOATS / 4; i += THREADS) Ws4[i] = Wg[i];
        if (tid < 10) s_b[tid] = b[tid];
    }

    unsigned long long acc[10];
    #pragma unroll
    for (int o = 0; o < 10; o++) acc[o] = 0ull;

    // ---- prefetch tile 0 into registers (7 float4 per thread) ----
    float4 stage[7];
    #pragma unroll
    for (int it = 0; it < 7; it++) {
        int j   = tid + it * THREADS;      // 0..1791 covers 128 imgs x 14 vec4
        int img = j / 14;
        int v   = j % 14;
        stage[it] = *(const float4*)(xg + img * 784 + v * 4);
    }
    __syncthreads();   // W ready

    #pragma unroll 1
    for (int r = 0; r < 14; r++) {
        // store staged tile (transposed: [k][img]) — stride 129 keeps banks clean
        #pragma unroll
        for (int it = 0; it < 7; it++) {
            int j   = tid + it * THREADS;
            int img = j / 14;
            int k   = (j % 14) * 4;
            s_px[(k + 0) * PX_STRIDE + img] = stage[it].x;
            s_px[(k + 1) * PX_STRIDE + img] = stage[it].y;
            s_px[(k + 2) * PX_STRIDE + img] = stage[it].z;
            s_px[(k + 3) * PX_STRIDE + img] = stage[it].w;
        }
        __syncthreads();

        // prefetch next tile (overlaps global latency with compute below)
        if (r < 13) {
            #pragma unroll
            for (int it = 0; it < 7; it++) {
                int j   = tid + it * THREADS;
                int img = j / 14;
                int v   = j % 14;
                stage[it] = *(const float4*)(xg + img * 784 + (r + 1) * 56 + v * 4);
            }
        }

        // compute: 7 patch columns per thread, warp-uniform (c,o) -> W LDS broadcast
        #pragma unroll
        for (int cc = 0; cc < 7; cc++) {
            const int c = cbase + cc;
            float p00 = s_px[(2 * c    ) * PX_STRIDE + imgcol];
            float p01 = s_px[(2 * c + 1) * PX_STRIDE + imgcol];
            float p10 = s_px[(28 + 2 * c) * PX_STRIDE + imgcol];
            float p11 = s_px[(29 + 2 * c) * PX_STRIDE + imgcol];
            float e0 = __cosf(p00);
            float e1 = e0 * __cosf(p01);
            float e2 = e1 * __cosf(p10);
            float e3 = e2 * __cosf(p11);
            unsigned long long e01 = pack2(e0, e1);
            unsigned long long e23 = pack2(e2, e3);
            const int p = r * 14 + c;
            const ulonglong2* wrow = (const ulonglong2*)s_W;
            #pragma unroll
            for (int o = 0; o < 10; o++) {
                ulonglong2 w = wrow[o * 196 + p];   // LDS.128 broadcast
                fma2(acc[o], e01, w.x);
                fma2(acc[o], e23, w.y);
            }
        }
        __syncthreads();
    }

    // ---- reduce f32x2 accumulators ----
    float accv[10];
    #pragma unroll
    for (int o = 0; o < 10; o++) {
        float2 a = unpack2(acc[o]);
        accv[o] = a.x + a.y;
    }

    // ---- merge the two column-halves via shared (aliases pixel buffer) ----
    if (chalf == 1) {
        #pragma unroll
        for (int o = 0; o < 10; o++) s_mg[imgcol * 11 + o] = accv[o];
    }
    __syncthreads();

    if (chalf == 0) {
        float l[10];
        float m = -INFINITY;
        #pragma unroll
        for (int o = 0; o < 10; o++) {
            l[o] = accv[o] + s_mg[imgcol * 11 + o] + s_b[o];
            m = fmaxf(m, l[o]);
        }
        float s = 0.f;
        #pragma unroll
        for (int o = 0; o < 10; o++) s += __expf(l[o] - m);
        float lse = m + __logf(s);
        float* op = out + (imgBase + imgcol) * 10;
        #pragma unroll
        for (int o = 0; o < 10; o++) op[o] = l[o] - lse;
    }
}

extern "C" void kernel_launch(void* const* d_in, const int* in_sizes, int n_in,
                              void* d_out, int out_size)
{
    const float* x = (const float*)d_in[0];
    const float* W = (const float*)d_in[1];
    const float* b = (const float*)d_in[2];
    float* out = (float*)d_out;

    const int B = in_sizes[0] / 784;               // 65536
    const int grid = B / IMGS_PER_BLK;             // 512
    const size_t smem = SMEM_FLOATS * sizeof(float);  // ~60.3 KB

    cudaFuncSetAttribute(quanv_kernel,
                         cudaFuncAttributeMaxDynamicSharedMemorySize, (int)smem);
    quanv_kernel<<<grid, THREADS, smem>>>(x, W, b, out);
}